// round 2
// baseline (speedup 1.0000x reference)
#include <cuda_runtime.h>
#include <cstdint>

// ============================================================================
// S6 forward, reduced:
//   y[t,d] = x[t,d] * softplus(U1[t,d] + b1[d]) * s[t]
//   s[t]   = sum_n (U2[t,n]+b2[n]) * (U3[t,n]+b3[n])
// where [U1|U2|U3] = x @ [W1|W2|W3]  -> one 8192x1024 @ 1024x1152 GEMM.
//
// Base sm_103 ISA only (NO tcgen05 — ptxas target rejects it):
//   cp.async 3-stage pipeline + mma.sync.m16n8k8 tf32.
// ============================================================================

#define NTOK   8192
#define DDIM   1024
#define NOUT   1152          // 9 tiles of 128; cols [1056,1152) are zero pad

#define BM     128
#define BN     128
#define BK     16
#define NKIT   (DDIM / BK)   // 64
#define GTHREADS 256

#define LDA    20            // A smem row pitch (floats): conflict-free frags
#define LDB    136           // B smem row pitch (floats): conflict-free frags
#define A_STAGE (BM * LDA)   // 2560 floats
#define B_STAGE (BK * LDB)   // 2176 floats
#define STAGES 3
#define SMEM_BYTES ((A_STAGE + B_STAGE) * STAGES * 4)   // 56832

__device__ float g_Wcat[(size_t)DDIM * NOUT];   // 4.7 MB packed [k][n], tf32-rounded
__device__ float g_U[(size_t)NTOK * NOUT];      // 37.7 MB GEMM output

// ---------------------------------------------------------------------------
// helpers
// ---------------------------------------------------------------------------
__device__ __forceinline__ uint32_t smem_u32(const void* p) {
    uint32_t a;
    asm("{ .reg .u64 t; cvta.to.shared.u64 t, %1; cvt.u32.u64 %0, t; }" : "=r"(a) : "l"(p));
    return a;
}
__device__ __forceinline__ void cp_async16(uint32_t dst, const float* src) {
    asm volatile("cp.async.cg.shared.global [%0], [%1], 16;" :: "r"(dst), "l"(src) : "memory");
}
__device__ __forceinline__ void cp_commit() {
    asm volatile("cp.async.commit_group;" ::: "memory");
}
template <int N>
__device__ __forceinline__ void cp_wait() {
    asm volatile("cp.async.wait_group %0;" :: "n"(N) : "memory");
}
__device__ __forceinline__ uint32_t f2tf(float x) {   // round-to-nearest tf32
    uint32_t u;
    asm("cvt.rna.tf32.f32 %0, %1;" : "=r"(u) : "f"(x));
    return u;
}
__device__ __forceinline__ float f2tf_f(float x) {
    float r;
    asm("{ .reg .b32 t; cvt.rna.tf32.f32 t, %1; mov.b32 %0, t; }" : "=f"(r) : "f"(x));
    return r;
}
__device__ __forceinline__ void mma_tf32(float* c, const uint32_t* a, const uint32_t* b) {
    asm volatile(
        "mma.sync.aligned.m16n8k8.row.col.f32.tf32.tf32.f32 "
        "{%0,%1,%2,%3}, {%4,%5,%6,%7}, {%8,%9}, {%0,%1,%2,%3};"
        : "+f"(c[0]), "+f"(c[1]), "+f"(c[2]), "+f"(c[3])
        : "r"(a[0]), "r"(a[1]), "r"(a[2]), "r"(a[3]), "r"(b[0]), "r"(b[1]));
}

// ---------------------------------------------------------------------------
// Kernel 1: pack Wcat[k][n] = [W1 | W2 | W3 | 0], tf32-rounded
// ---------------------------------------------------------------------------
__global__ void __launch_bounds__(256) s6_pack(const float* __restrict__ W1,
                                               const float* __restrict__ W2,
                                               const float* __restrict__ W3) {
    const int idx = blockIdx.x * 256 + threadIdx.x;
    if (idx >= DDIM * NOUT) return;
    const int k = idx / NOUT;
    const int n = idx - k * NOUT;
    float v = 0.0f;
    if (n < 1024)       v = W1[(size_t)k * 1024 + n];
    else if (n < 1040)  v = W2[(size_t)k * 16 + (n - 1024)];
    else if (n < 1056)  v = W3[(size_t)k * 16 + (n - 1040)];
    g_Wcat[idx] = f2tf_f(v);
}

// ---------------------------------------------------------------------------
// Kernel 2: tf32 mma.sync GEMM  U[8192,1152] = X[8192,1024] @ Wcat
// ---------------------------------------------------------------------------
__device__ __forceinline__ void prefetch_stage(const float* __restrict__ X,
                                               uint32_t aBaseSm, uint32_t bBaseSm,
                                               int kt, int m0, int n0, int tid) {
    const int k0 = kt * BK;
    // A: 128 rows x 16 floats = 512 x 16B chunks
#pragma unroll
    for (int i = 0; i < 2; ++i) {
        const int c = tid + i * GTHREADS;
        const int row = c >> 2, kc = c & 3;
        cp_async16(aBaseSm + (uint32_t)(row * LDA + kc * 4) * 4,
                   X + (size_t)(m0 + row) * DDIM + k0 + kc * 4);
    }
    // B: 16 rows x 128 floats = 512 x 16B chunks
#pragma unroll
    for (int i = 0; i < 2; ++i) {
        const int c = tid + i * GTHREADS;
        const int krow = c >> 5, nc = c & 31;
        cp_async16(bBaseSm + (uint32_t)(krow * LDB + nc * 4) * 4,
                   g_Wcat + (size_t)(k0 + krow) * NOUT + n0 + nc * 4);
    }
}

__global__ void __launch_bounds__(GTHREADS, 1) s6_gemm(const float* __restrict__ X) {
    extern __shared__ float smem[];
    float* sA = smem;                       // 3 stages of A
    float* sB = smem + STAGES * A_STAGE;    // 3 stages of B
    const uint32_t sA_u = smem_u32(sA);
    const uint32_t sB_u = smem_u32(sB);

    const int tid = threadIdx.x;
    const int wid = tid >> 5;
    const int lane = tid & 31;
    const int grp = lane >> 2;     // 0..7
    const int qid = lane & 3;      // 0..3
    const int wm = wid & 1;        // 2 warps along M
    const int wn = wid >> 1;       // 4 warps along N
    const int m0 = blockIdx.y * BM;
    const int n0 = blockIdx.x * BN;

    // per-thread fragment bases (float indices within a stage)
    const int aBase = (wm * 64 + grp) * LDA + qid;
    const int bBase = qid * LDB + wn * 32 + grp;

    float acc[4][4][4];
#pragma unroll
    for (int f = 0; f < 4; ++f)
#pragma unroll
        for (int g = 0; g < 4; ++g)
#pragma unroll
            for (int q = 0; q < 4; ++q) acc[f][g][q] = 0.0f;

    // prologue
    prefetch_stage(X, sA_u, sB_u, 0, m0, n0, tid);
    cp_commit();
    prefetch_stage(X, sA_u + A_STAGE * 4, sB_u + B_STAGE * 4, 1, m0, n0, tid);
    cp_commit();

    for (int kt = 0; kt < NKIT; ++kt) {
        const int s = kt % STAGES;
        cp_wait<1>();
        __syncthreads();

        const int pf = kt + 2;
        if (pf < NKIT) {
            const int ps = pf % STAGES;
            prefetch_stage(X, sA_u + (uint32_t)ps * A_STAGE * 4,
                           sB_u + (uint32_t)ps * B_STAGE * 4, pf, m0, n0, tid);
        }
        cp_commit();

        const float* sAs = sA + s * A_STAGE;
        const float* sBs = sB + s * B_STAGE;
#pragma unroll
        for (int ks = 0; ks < 2; ++ks) {
            uint32_t af[4][4], bf[4][2];
#pragma unroll
            for (int f = 0; f < 4; ++f) {
                const float* p = sAs + aBase + f * 16 * LDA + ks * 8;
                af[f][0] = f2tf(p[0]);
                af[f][1] = f2tf(p[8 * LDA]);
                af[f][2] = f2tf(p[4]);
                af[f][3] = f2tf(p[8 * LDA + 4]);
            }
#pragma unroll
            for (int g = 0; g < 4; ++g) {
                const uint32_t* p = (const uint32_t*)(sBs + bBase + ks * 8 * LDB + g * 8);
                bf[g][0] = p[0];
                bf[g][1] = p[4 * LDB];
            }
#pragma unroll
            for (int f = 0; f < 4; ++f)
#pragma unroll
                for (int g = 0; g < 4; ++g)
                    mma_tf32(acc[f][g], af[f], bf[g]);
        }
    }

    // store D -> g_U
#pragma unroll
    for (int f = 0; f < 4; ++f) {
        const size_t r0 = (size_t)(m0 + wm * 64 + f * 16 + grp);
#pragma unroll
        for (int g = 0; g < 4; ++g) {
            const int c0 = n0 + wn * 32 + g * 8 + qid * 2;
            float2 v0 = make_float2(acc[f][g][0], acc[f][g][1]);
            float2 v1 = make_float2(acc[f][g][2], acc[f][g][3]);
            *(float2*)(g_U + r0 * NOUT + c0) = v0;
            *(float2*)(g_U + (r0 + 8) * NOUT + c0) = v1;
        }
    }
}

// ---------------------------------------------------------------------------
// Kernel 3: epilogue  y = x * softplus(U1 + b1) * sum_n (U2+b2)(U3+b3)
// ---------------------------------------------------------------------------
__device__ __forceinline__ float softplus_f(float z) {
    return fmaxf(z, 0.0f) + log1pf(expf(-fabsf(z)));
}

__global__ void __launch_bounds__(128) s6_epilogue(const float* __restrict__ x,
                                                   const float* __restrict__ b1,
                                                   const float* __restrict__ b2,
                                                   const float* __restrict__ b3,
                                                   float* __restrict__ y) {
    const int t = blockIdx.x;
    const int tid = threadIdx.x;
    const float* Ur = g_U + (size_t)t * NOUT;
    __shared__ float s_sh;

    if (tid < 32) {
        float p = 0.0f;
        if (tid < 16) {
            float Bv = Ur[1024 + tid] + b2[tid];
            float Cv = Ur[1040 + tid] + b3[tid];
            p = Bv * Cv;
        }
#pragma unroll
        for (int o = 8; o > 0; o >>= 1) p += __shfl_down_sync(0xffffffffu, p, o);
        if (tid == 0) s_sh = p;
    }
    __syncthreads();
    const float s = s_sh;

    const float4* x4  = (const float4*)(x + (size_t)t * DDIM);
    const float4* u4  = (const float4*)Ur;
    const float4* b14 = (const float4*)b1;
    float4* y4 = (float4*)(y + (size_t)t * DDIM);
#pragma unroll
    for (int i = 0; i < 2; ++i) {
        const int idx = tid + i * 128;
        const float4 xv = x4[idx];
        const float4 uv = u4[idx];
        const float4 bv = b14[idx];
        float4 r;
        r.x = xv.x * softplus_f(uv.x + bv.x) * s;
        r.y = xv.y * softplus_f(uv.y + bv.y) * s;
        r.z = xv.z * softplus_f(uv.z + bv.z) * s;
        r.w = xv.w * softplus_f(uv.w + bv.w) * s;
        y4[idx] = r;
    }
}

// ---------------------------------------------------------------------------
// Launch
// ---------------------------------------------------------------------------
extern "C" void kernel_launch(void* const* d_in, const int* in_sizes, int n_in,
                              void* d_out, int out_size) {
    const float* x  = (const float*)d_in[0];
    const float* W1 = (const float*)d_in[1];
    const float* b1 = (const float*)d_in[2];
    const float* W2 = (const float*)d_in[3];
    const float* b2 = (const float*)d_in[4];
    const float* W3 = (const float*)d_in[5];
    const float* b3 = (const float*)d_in[6];
    float* y = (float*)d_out;

    s6_pack<<<(DDIM * NOUT + 255) / 256, 256>>>(W1, W2, W3);

    cudaFuncSetAttribute(s6_gemm, cudaFuncAttributeMaxDynamicSharedMemorySize, SMEM_BYTES);
    s6_gemm<<<dim3(NOUT / BN, NTOK / BM), GTHREADS, SMEM_BYTES>>>(x);

    s6_epilogue<<<NTOK, 128>>>(x, b1, b2, b3, y);
}

// round 3
// speedup vs baseline: 1.4114x; 1.4114x over previous
#include <cuda_runtime.h>
#include <cuda_fp16.h>
#include <cstdint>

// ============================================================================
// S6 forward, reduced:
//   y[t,d] = x[t,d] * softplus(U1[t,d] + b1[d]) * s[t]
//   s[t]   = sum_n (U2[t,n]+b2[n]) * (U3[t,n]+b3[n])
// Pipeline (all fp16 tensor-core, fp32 accum; base sm_103 ISA — no tcgen05):
//   1. pack:   W1 -> g_Wh  [n][k] fp16 (transposed), W2|W3 -> g_W23h [32][k]
//   2. cvtx:   x -> g_Xh fp16
//   3. scomp:  g_s[t] = sum_n (U2+b2)(U3+b3)   (skinny 8192x32x1024 mma GEMM)
//   4. gemm:   U1 = Xh @ Wh^T via m16n8k16, epilogue fused -> y  (no g_U!)
// ============================================================================

#define NTOK   8192
#define DDIM   1024

#define BM     128
#define BN     128
#define BK     32
#define NKIT   (DDIM / BK)   // 32
#define GTHREADS 256

#define PITCH_H   56         // smem row pitch in halves (112B): conflict-free + 16B aligned
#define A_STAGE_H (128 * PITCH_H)                 // 7168 halves
#define G_STAGE_H (2 * A_STAGE_H)                 // A + B per stage
#define G_SMEM_BYTES (3 * G_STAGE_H * 2)          // 86016

// scomp smem: W23 resident [32][1032] + 3-stage A [128][56]
#define SW_PITCH_H 1032
#define SC_SMEM_BYTES ((32 * SW_PITCH_H + 3 * A_STAGE_H) * 2)   // 109056

__device__ __half g_Wh[(size_t)DDIM * DDIM];     // W1^T, [n][k], 2 MB
__device__ __half g_W23h[32 * DDIM];             // [n][k], n<16: W2 col, n>=16: W3 col
__device__ __half g_Xh[(size_t)NTOK * DDIM];     // x in fp16, 16.8 MB
__device__ float  g_s[NTOK];

// ---------------------------------------------------------------------------
// helpers
// ---------------------------------------------------------------------------
__device__ __forceinline__ uint32_t smem_u32(const void* p) {
    uint32_t a;
    asm("{ .reg .u64 t; cvta.to.shared.u64 t, %1; cvt.u32.u64 %0, t; }" : "=r"(a) : "l"(p));
    return a;
}
__device__ __forceinline__ void cp_async16(uint32_t dst, const void* src) {
    asm volatile("cp.async.cg.shared.global [%0], [%1], 16;" :: "r"(dst), "l"(src) : "memory");
}
__device__ __forceinline__ void cp_commit() {
    asm volatile("cp.async.commit_group;" ::: "memory");
}
template <int N>
__device__ __forceinline__ void cp_wait() {
    asm volatile("cp.async.wait_group %0;" :: "n"(N) : "memory");
}
__device__ __forceinline__ void mma_f16(float* c, const uint32_t* a, const uint32_t* b) {
    asm volatile(
        "mma.sync.aligned.m16n8k16.row.col.f32.f16.f16.f32 "
        "{%0,%1,%2,%3}, {%4,%5,%6,%7}, {%8,%9}, {%0,%1,%2,%3};"
        : "+f"(c[0]), "+f"(c[1]), "+f"(c[2]), "+f"(c[3])
        : "r"(a[0]), "r"(a[1]), "r"(a[2]), "r"(a[3]), "r"(b[0]), "r"(b[1]));
}
__device__ __forceinline__ float softplus_f(float z) {
    return fmaxf(z, 0.0f) + __logf(1.0f + __expf(-fabsf(z)));
}

// ---------------------------------------------------------------------------
// Kernel 1a: Wh[n][k] = fp16(W1[k][n])   (transpose 1024x1024)
// ---------------------------------------------------------------------------
__global__ void __launch_bounds__(1024) s6_pack_w1(const float* __restrict__ W1) {
    __shared__ float tile[32][33];
    const int tx = threadIdx.x, ty = threadIdx.y;
    const int k = blockIdx.y * 32 + ty;
    const int n = blockIdx.x * 32 + tx;
    tile[ty][tx] = W1[(size_t)k * DDIM + n];
    __syncthreads();
    const int nn = blockIdx.x * 32 + ty;
    const int kk = blockIdx.y * 32 + tx;
    g_Wh[(size_t)nn * DDIM + kk] = __float2half_rn(tile[tx][ty]);
}

// ---------------------------------------------------------------------------
// Kernel 1b: W23h[n][k]: n<16 -> W2[k][n], n>=16 -> W3[k][n-16]
// ---------------------------------------------------------------------------
__global__ void __launch_bounds__(256) s6_pack_w23(const float* __restrict__ W2,
                                                   const float* __restrict__ W3) {
    const int idx = blockIdx.x * 256 + threadIdx.x;   // 32768 total
    const int n = idx >> 10;
    const int k = idx & 1023;
    const float v = (n < 16) ? W2[(size_t)k * 16 + n] : W3[(size_t)k * 16 + (n - 16)];
    g_W23h[n * DDIM + k] = __float2half_rn(v);
}

// ---------------------------------------------------------------------------
// Kernel 2: g_Xh = fp16(x)
// ---------------------------------------------------------------------------
__global__ void __launch_bounds__(256) s6_cvtx(const float* __restrict__ x) {
    const int i = blockIdx.x * 256 + threadIdx.x;     // half2 index, 4194304 total
    const float2 v = ((const float2*)x)[i];
    ((__half2*)g_Xh)[i] = __float22half2_rn(v);
}

// ---------------------------------------------------------------------------
// Kernel 3: scomp — s[t] = sum_{n<16} (U2[t,n]+b2[n]) * (U3[t,n]+b3[n])
//   per CTA: 128 tokens, 8 warps x 16 tokens; W23 resident in smem
// ---------------------------------------------------------------------------
__global__ void __launch_bounds__(256) s6_scomp(const float* __restrict__ b2,
                                                const float* __restrict__ b3) {
    extern __shared__ __half sm[];
    __half* sW = sm;                          // [32][1032]
    __half* sA = sm + 32 * SW_PITCH_H;        // 3 stages [128][56]
    const uint32_t sA_u = smem_u32(sA);

    const int tid = threadIdx.x;
    const int wid = tid >> 5;
    const int lane = tid & 31;
    const int grp = lane >> 2;
    const int qid = lane & 3;
    const int tok0 = blockIdx.x * 128;

    // prologue: prefetch A stages 0,1 (each: 128 rows x 4 x 16B chunks)
#pragma unroll
    for (int st = 0; st < 2; ++st) {
#pragma unroll
        for (int i = 0; i < 2; ++i) {
            const int c = tid + i * 256;
            const int row = c >> 2, ch = c & 3;
            cp_async16(sA_u + (uint32_t)(st * A_STAGE_H + row * PITCH_H) * 2 + ch * 16,
                       g_Xh + (size_t)(tok0 + row) * DDIM + st * BK + ch * 8);
        }
        cp_commit();
    }

    // load W23 into smem (u32 copies)
    for (int i = tid; i < 32 * 512; i += 256) {
        const int r = i >> 9, w = i & 511;
        ((uint32_t*)sW)[r * (SW_PITCH_H / 2) + w] = ((const uint32_t*)g_W23h)[r * 512 + w];
    }

    float acc[4][4];
#pragma unroll
    for (int nf = 0; nf < 4; ++nf)
#pragma unroll
        for (int q = 0; q < 4; ++q) acc[nf][q] = 0.0f;

    for (int kt = 0; kt < NKIT; ++kt) {
        const int s = kt % 3;
        cp_wait<1>();
        __syncthreads();

        const int pf = kt + 2;
        if (pf < NKIT) {
            const int ps = pf % 3;
#pragma unroll
            for (int i = 0; i < 2; ++i) {
                const int c = tid + i * 256;
                const int row = c >> 2, ch = c & 3;
                cp_async16(sA_u + (uint32_t)(ps * A_STAGE_H + row * PITCH_H) * 2 + ch * 16,
                           g_Xh + (size_t)(tok0 + row) * DDIM + pf * BK + ch * 8);
            }
        }
        cp_commit();

        const __half* sAw = sA + s * A_STAGE_H + (wid * 16 + grp) * PITCH_H;
#pragma unroll
        for (int ks = 0; ks < 2; ++ks) {
            const int koff = ks * 16 + 2 * qid;
            uint32_t a[4];
            a[0] = *(const uint32_t*)(sAw + koff);
            a[1] = *(const uint32_t*)(sAw + 8 * PITCH_H + koff);
            a[2] = *(const uint32_t*)(sAw + koff + 8);
            a[3] = *(const uint32_t*)(sAw + 8 * PITCH_H + koff + 8);
            const int kg = kt * BK + koff;
#pragma unroll
            for (int nf = 0; nf < 4; ++nf) {
                uint32_t b[2];
                const __half* pw = sW + (nf * 8 + grp) * SW_PITCH_H + kg;
                b[0] = *(const uint32_t*)pw;
                b[1] = *(const uint32_t*)(pw + 8);
                mma_f16(acc[nf], a, b);
            }
        }
    }

    // epilogue: pair col n (B part, nf 0..1) with col n+16 (C part, nf 2..3)
    float p0 = 0.0f, p1 = 0.0f;
#pragma unroll
    for (int nf = 0; nf < 2; ++nf) {
#pragma unroll
        for (int i = 0; i < 2; ++i) {
            const int n = nf * 8 + 2 * qid + i;
            const float bB = __ldg(b2 + n), bC = __ldg(b3 + n);
            p0 += (acc[nf][i]     + bB) * (acc[nf + 2][i]     + bC);
            p1 += (acc[nf][i + 2] + bB) * (acc[nf + 2][i + 2] + bC);
        }
    }
    p0 += __shfl_xor_sync(0xffffffffu, p0, 1);
    p0 += __shfl_xor_sync(0xffffffffu, p0, 2);
    p1 += __shfl_xor_sync(0xffffffffu, p1, 1);
    p1 += __shfl_xor_sync(0xffffffffu, p1, 2);
    if (qid == 0) {
        g_s[tok0 + wid * 16 + grp]     = p0;
        g_s[tok0 + wid * 16 + grp + 8] = p1;
    }
}

// ---------------------------------------------------------------------------
// Kernel 4: main GEMM (fp16 m16n8k16) + fused epilogue -> y
//   CTA 128x128, BK=32, 3-stage cp.async, 8 warps (2x4), warp tile 64x32
// ---------------------------------------------------------------------------
__device__ __forceinline__ void g_prefetch(uint32_t smem_base_u, int stage, int kt,
                                           int m0, int n0, int tid) {
    const uint32_t st = smem_base_u + (uint32_t)(stage * G_STAGE_H) * 2;
#pragma unroll
    for (int i = 0; i < 2; ++i) {           // A: 128 rows x 4 chunks
        const int c = tid + i * GTHREADS;
        const int row = c >> 2, ch = c & 3;
        cp_async16(st + (uint32_t)(row * PITCH_H) * 2 + ch * 16,
                   g_Xh + (size_t)(m0 + row) * DDIM + kt * BK + ch * 8);
    }
#pragma unroll
    for (int i = 0; i < 2; ++i) {           // B: 128 rows x 4 chunks
        const int c = tid + i * GTHREADS;
        const int row = c >> 2, ch = c & 3;
        cp_async16(st + (uint32_t)(A_STAGE_H + row * PITCH_H) * 2 + ch * 16,
                   g_Wh + (size_t)(n0 + row) * DDIM + kt * BK + ch * 8);
    }
}

__global__ void __launch_bounds__(GTHREADS, 2) s6_gemm(const float* __restrict__ x,
                                                       const float* __restrict__ b1,
                                                       float* __restrict__ y) {
    extern __shared__ __half smh[];
    const uint32_t sm_u = smem_u32(smh);

    const int tid = threadIdx.x;
    const int wid = tid >> 5;
    const int lane = tid & 31;
    const int grp = lane >> 2;
    const int qid = lane & 3;
    const int wm = wid & 1;      // 2 warps along M (64 each)
    const int wn = wid >> 1;     // 4 warps along N (32 each)
    const int m0 = blockIdx.y * BM;
    const int n0 = blockIdx.x * BN;

    float acc[4][4][4];
#pragma unroll
    for (int f = 0; f < 4; ++f)
#pragma unroll
        for (int g = 0; g < 4; ++g)
#pragma unroll
            for (int q = 0; q < 4; ++q) acc[f][g][q] = 0.0f;

    g_prefetch(sm_u, 0, 0, m0, n0, tid);
    cp_commit();
    g_prefetch(sm_u, 1, 1, m0, n0, tid);
    cp_commit();

    const int aRow = wm * 64 + grp;
    const int bRow = wn * 32 + grp;

    for (int kt = 0; kt < NKIT; ++kt) {
        const int s = kt % 3;
        cp_wait<1>();
        __syncthreads();

        const int pf = kt + 2;
        if (pf < NKIT) g_prefetch(sm_u, pf % 3, pf, m0, n0, tid);
        cp_commit();

        const __half* sAs = smh + s * G_STAGE_H;
        const __half* sBs = sAs + A_STAGE_H;
#pragma unroll
        for (int ks = 0; ks < 2; ++ks) {
            const int koff = ks * 16 + 2 * qid;
            uint32_t af[4][4], bf[4][2];
#pragma unroll
            for (int f = 0; f < 4; ++f) {
                const __half* p = sAs + (aRow + f * 16) * PITCH_H + koff;
                af[f][0] = *(const uint32_t*)p;
                af[f][1] = *(const uint32_t*)(p + 8 * PITCH_H);
                af[f][2] = *(const uint32_t*)(p + 8);
                af[f][3] = *(const uint32_t*)(p + 8 * PITCH_H + 8);
            }
#pragma unroll
            for (int g = 0; g < 4; ++g) {
                const __half* p = sBs + (bRow + g * 8) * PITCH_H + koff;
                bf[g][0] = *(const uint32_t*)p;
                bf[g][1] = *(const uint32_t*)(p + 8);
            }
#pragma unroll
            for (int f = 0; f < 4; ++f)
#pragma unroll
                for (int g = 0; g < 4; ++g)
                    mma_f16(acc[f][g], af[f], bf[g]);
        }
    }

    // fused epilogue: y = x * softplus(acc + b1) * s
#pragma unroll
    for (int f = 0; f < 4; ++f) {
        const int r0 = m0 + wm * 64 + f * 16 + grp;
        const int r1 = r0 + 8;
        const float s0 = __ldg(g_s + r0);
        const float s1 = __ldg(g_s + r1);
        const float* xr0 = x + (size_t)r0 * DDIM;
        const float* xr1 = x + (size_t)r1 * DDIM;
        float* yr0 = y + (size_t)r0 * DDIM;
        float* yr1 = y + (size_t)r1 * DDIM;
#pragma unroll
        for (int g = 0; g < 4; ++g) {
            const int c = n0 + wn * 32 + g * 8 + 2 * qid;
            const float2 bv = *(const float2*)(b1 + c);
            const float2 x0 = *(const float2*)(xr0 + c);
            const float2 x1 = *(const float2*)(xr1 + c);
            float2 o0, o1;
            o0.x = x0.x * softplus_f(acc[f][g][0] + bv.x) * s0;
            o0.y = x0.y * softplus_f(acc[f][g][1] + bv.y) * s0;
            o1.x = x1.x * softplus_f(acc[f][g][2] + bv.x) * s1;
            o1.y = x1.y * softplus_f(acc[f][g][3] + bv.y) * s1;
            *(float2*)(yr0 + c) = o0;
            *(float2*)(yr1 + c) = o1;
        }
    }
}

// ---------------------------------------------------------------------------
// Launch
// ---------------------------------------------------------------------------
extern "C" void kernel_launch(void* const* d_in, const int* in_sizes, int n_in,
                              void* d_out, int out_size) {
    const float* x  = (const float*)d_in[0];
    const float* W1 = (const float*)d_in[1];
    const float* b1 = (const float*)d_in[2];
    const float* W2 = (const float*)d_in[3];
    const float* b2 = (const float*)d_in[4];
    const float* W3 = (const float*)d_in[5];
    const float* b3 = (const float*)d_in[6];
    float* y = (float*)d_out;

    s6_pack_w1<<<dim3(32, 32), dim3(32, 32)>>>(W1);
    s6_pack_w23<<<128, 256>>>(W2, W3);
    s6_cvtx<<<(NTOK * DDIM / 2) / 256, 256>>>(x);

    cudaFuncSetAttribute(s6_scomp, cudaFuncAttributeMaxDynamicSharedMemorySize, SC_SMEM_BYTES);
    s6_scomp<<<NTOK / 128, 256, SC_SMEM_BYTES>>>(b2, b3);

    cudaFuncSetAttribute(s6_gemm, cudaFuncAttributeMaxDynamicSharedMemorySize, G_SMEM_BYTES);
    s6_gemm<<<dim3(DDIM / BN, NTOK / BM), GTHREADS, G_SMEM_BYTES>>>(x, b1, y);
}

// round 5
// speedup vs baseline: 1.4847x; 1.0519x over previous
#include <cuda_runtime.h>
#include <cuda_fp16.h>
#include <cstdint>

// ============================================================================
// S6 forward, reduced:
//   y[t,d] = x[t,d] * softplus(U1[t,d] + b1[d]) * s[t]
//   s[t]   = sum_n (U2[t,n]+b2[n]) * (U3[t,n]+b3[n])
// Pipeline (fp16 tensor-core, fp32 accum; base sm_103 ISA — no tcgen05):
//   1. pack_w1:  W1 -> g_Wh [n][k] fp16 (transposed)
//   2. pack_w23: W2|W3 -> g_W23h [32][k] fp16
//   3. prep:     x -> g_Xh fp16  AND  g_s[t] (fused convert + skinny GEMM)
//   4. gemm:     U1 = Xh @ Wh^T (m16n8k16, 128x64 tiles), fused epilogue -> y
// ============================================================================

#define NTOK   8192
#define DDIM   1024

#define BM     128
#define BN     64
#define BK     32
#define NKIT   (DDIM / BK)   // 32
#define GTHREADS 256

#define PITCH_H   40         // gemm smem row pitch (halves) = 80B: 16B-aligned, conflict-free
#define A_STAGE_H (BM * PITCH_H)               // 5120 halves
#define B_STAGE_H (BN * PITCH_H)               // 2560 halves
#define G_STAGE_H (A_STAGE_H + B_STAGE_H)      // 7680
#define G_SMEM_BYTES (3 * G_STAGE_H * 2)       // 46080

__device__ __half g_Wh[(size_t)DDIM * DDIM];   // W1^T, [n][k], 2 MB
__device__ __half g_W23h[32 * DDIM];           // [n][k]: n<16 W2 col, n>=16 W3 col
__device__ __half g_Xh[(size_t)NTOK * DDIM];   // x fp16, 16.8 MB
__device__ float  g_s[NTOK];

// ---------------------------------------------------------------------------
// helpers
// ---------------------------------------------------------------------------
__device__ __forceinline__ uint32_t smem_u32(const void* p) {
    uint32_t a;
    asm("{ .reg .u64 t; cvta.to.shared.u64 t, %1; cvt.u32.u64 %0, t; }" : "=r"(a) : "l"(p));
    return a;
}
__device__ __forceinline__ uint32_t h2_u32(__half2 h) {
    union { __half2 h; uint32_t u; } cvt;
    cvt.h = h;
    return cvt.u;
}
__device__ __forceinline__ void cp_async16(uint32_t dst, const void* src) {
    asm volatile("cp.async.cg.shared.global [%0], [%1], 16;" :: "r"(dst), "l"(src) : "memory");
}
__device__ __forceinline__ void cp_commit() {
    asm volatile("cp.async.commit_group;" ::: "memory");
}
template <int N>
__device__ __forceinline__ void cp_wait() {
    asm volatile("cp.async.wait_group %0;" :: "n"(N) : "memory");
}
__device__ __forceinline__ void mma_f16(float* c, const uint32_t* a, const uint32_t* b) {
    asm volatile(
        "mma.sync.aligned.m16n8k16.row.col.f32.f16.f16.f32 "
        "{%0,%1,%2,%3}, {%4,%5,%6,%7}, {%8,%9}, {%0,%1,%2,%3};"
        : "+f"(c[0]), "+f"(c[1]), "+f"(c[2]), "+f"(c[3])
        : "r"(a[0]), "r"(a[1]), "r"(a[2]), "r"(a[3]), "r"(b[0]), "r"(b[1]));
}
__device__ __forceinline__ float softplus_f(float z) {
    return fmaxf(z, 0.0f) + __logf(1.0f + __expf(-fabsf(z)));
}

// ---------------------------------------------------------------------------
// Kernel 1a: Wh[n][k] = fp16(W1[k][n])
// ---------------------------------------------------------------------------
__global__ void __launch_bounds__(1024) s6_pack_w1(const float* __restrict__ W1) {
    __shared__ float tile[32][33];
    const int tx = threadIdx.x, ty = threadIdx.y;
    const int k = blockIdx.y * 32 + ty;
    const int n = blockIdx.x * 32 + tx;
    tile[ty][tx] = W1[(size_t)k * DDIM + n];
    __syncthreads();
    const int nn = blockIdx.x * 32 + ty;
    const int kk = blockIdx.y * 32 + tx;
    g_Wh[(size_t)nn * DDIM + kk] = __float2half_rn(tile[tx][ty]);
}

// ---------------------------------------------------------------------------
// Kernel 1b: W23h[n][k]
// ---------------------------------------------------------------------------
__global__ void __launch_bounds__(256) s6_pack_w23(const float* __restrict__ W2,
                                                   const float* __restrict__ W3) {
    const int idx = blockIdx.x * 256 + threadIdx.x;   // 32768
    const int n = idx >> 10;
    const int k = idx & 1023;
    const float v = (n < 16) ? W2[(size_t)k * 16 + n] : W3[(size_t)k * 16 + (n - 16)];
    g_W23h[n * DDIM + k] = __float2half_rn(v);
}

// ---------------------------------------------------------------------------
// Kernel 2: prep — fused x->fp16 convert + s[t] computation
//   256 CTAs x 32 tokens; K in 8 chunks of 128; 8 warps = 8 k16 slices/chunk
// ---------------------------------------------------------------------------
#define P_PITCH 136                   // halves; 272B rows -> conflict-free frags
#define P_STG   (32 * P_PITCH)        // 4352 halves per stage

__global__ void __launch_bounds__(256) s6_prep(const float* __restrict__ x,
                                               const float* __restrict__ b2,
                                               const float* __restrict__ b3) {
    __shared__ __half sX[2][P_STG];
    __shared__ __half sW[2][P_STG];
    __shared__ float sU[32][33];

    const int tid = threadIdx.x;
    const int wid = tid >> 5;
    const int lane = tid & 31;
    const int grp = lane >> 2;
    const int qid = lane & 3;
    const int tok0 = blockIdx.x * 32;
    const uint32_t sW_u[2] = { smem_u32(sW[0]), smem_u32(sW[1]) };

    // zero sU
    for (int i = tid; i < 32 * 33; i += 256) ((float*)sU)[i] = 0.0f;

    // preload W chunk 0
#pragma unroll
    for (int j = 0; j < 2; ++j) {
        const int i = tid + j * 256;
        const int row = i >> 4, ch = i & 15;
        cp_async16(sW_u[0] + (uint32_t)(row * P_PITCH + ch * 8) * 2,
                   g_W23h + row * DDIM + ch * 8);
    }
    cp_commit();

    const int t = tid >> 3;            // token handled by this thread (x convert)
    const int co = (tid & 7) * 16;     // col offset within chunk (floats/halves)

    float acc[2][4][4];
#pragma unroll
    for (int f = 0; f < 2; ++f)
#pragma unroll
        for (int g = 0; g < 4; ++g)
#pragma unroll
            for (int q = 0; q < 4; ++q) acc[f][g][q] = 0.0f;

    for (int c = 0; c < 8; ++c) {
        const int st = c & 1;
        // load x chunk c (fp32), convert, store to sX + g_Xh
        const float* src = x + (size_t)(tok0 + t) * DDIM + c * 128 + co;
        float4 v0 = *(const float4*)(src + 0);
        float4 v1 = *(const float4*)(src + 4);
        float4 v2 = *(const float4*)(src + 8);
        float4 v3 = *(const float4*)(src + 12);
        uint4 pk0, pk1;
        pk0.x = h2_u32(__float22half2_rn(make_float2(v0.x, v0.y)));
        pk0.y = h2_u32(__float22half2_rn(make_float2(v0.z, v0.w)));
        pk0.z = h2_u32(__float22half2_rn(make_float2(v1.x, v1.y)));
        pk0.w = h2_u32(__float22half2_rn(make_float2(v1.z, v1.w)));
        pk1.x = h2_u32(__float22half2_rn(make_float2(v2.x, v2.y)));
        pk1.y = h2_u32(__float22half2_rn(make_float2(v2.z, v2.w)));
        pk1.z = h2_u32(__float22half2_rn(make_float2(v3.x, v3.y)));
        pk1.w = h2_u32(__float22half2_rn(make_float2(v3.z, v3.w)));
        *(uint4*)(&sX[st][t * P_PITCH + co])     = pk0;
        *(uint4*)(&sX[st][t * P_PITCH + co + 8]) = pk1;
        __half* gx = g_Xh + (size_t)(tok0 + t) * DDIM + c * 128 + co;
        *(uint4*)(gx)     = pk0;
        *(uint4*)(gx + 8) = pk1;

        cp_wait<0>();
        __syncthreads();   // sW[st] ready, sX[st] visible, prior mma done

        if (c < 7) {       // prefetch next W chunk
            const int ns = (c + 1) & 1;
#pragma unroll
            for (int j = 0; j < 2; ++j) {
                const int i = tid + j * 256;
                const int row = i >> 4, ch = i & 15;
                cp_async16(sW_u[ns] + (uint32_t)(row * P_PITCH + ch * 8) * 2,
                           g_W23h + row * DDIM + (c + 1) * 128 + ch * 8);
            }
            cp_commit();
        }

        // mma: this warp handles k16 slice `wid` of the chunk
        const int koff = wid * 16 + 2 * qid;
#pragma unroll
        for (int f = 0; f < 2; ++f) {
            const __half* p = &sX[st][(f * 16 + grp) * P_PITCH + koff];
            uint32_t a[4];
            a[0] = *(const uint32_t*)p;
            a[1] = *(const uint32_t*)(p + 8 * P_PITCH);
            a[2] = *(const uint32_t*)(p + 8);
            a[3] = *(const uint32_t*)(p + 8 * P_PITCH + 8);
#pragma unroll
            for (int g = 0; g < 4; ++g) {
                const __half* q = &sW[st][(g * 8 + grp) * P_PITCH + koff];
                uint32_t b[2];
                b[0] = *(const uint32_t*)q;
                b[1] = *(const uint32_t*)(q + 8);
                mma_f16(acc[f][g], a, b);
            }
        }
        __syncthreads();   // protect sX[st] rewrite at c+2
    }

    // cross-warp reduce via smem atomics
#pragma unroll
    for (int f = 0; f < 2; ++f)
#pragma unroll
        for (int g = 0; g < 4; ++g) {
            atomicAdd(&sU[f * 16 + grp][g * 8 + 2 * qid],         acc[f][g][0]);
            atomicAdd(&sU[f * 16 + grp][g * 8 + 2 * qid + 1],     acc[f][g][1]);
            atomicAdd(&sU[f * 16 + grp + 8][g * 8 + 2 * qid],     acc[f][g][2]);
            atomicAdd(&sU[f * 16 + grp + 8][g * 8 + 2 * qid + 1], acc[f][g][3]);
        }
    __syncthreads();

    if (tid < 32) {
        float s = 0.0f;
#pragma unroll
        for (int n = 0; n < 16; ++n)
            s += (sU[tid][n] + __ldg(b2 + n)) * (sU[tid][n + 16] + __ldg(b3 + n));
        g_s[tok0 + tid] = s;
    }
}

// ---------------------------------------------------------------------------
// Kernel 3: main GEMM (fp16 m16n8k16, 128x64 tiles) + fused epilogue -> y
// ---------------------------------------------------------------------------
__device__ __forceinline__ void g_prefetch(uint32_t smem_base_u, int stage, int kt,
                                           int m0, int n0, int tid) {
    const uint32_t st = smem_base_u + (uint32_t)(stage * G_STAGE_H) * 2;
    // A: 128 rows x 4 x 16B
#pragma unroll
    for (int i = 0; i < 2; ++i) {
        const int c = tid + i * GTHREADS;
        const int row = c >> 2, ch = c & 3;
        cp_async16(st + (uint32_t)(row * PITCH_H + ch * 8) * 2,
                   g_Xh + (size_t)(m0 + row) * DDIM + kt * BK + ch * 8);
    }
    // B: 64 rows x 4 x 16B
    {
        const int row = tid >> 2, ch = tid & 3;
        cp_async16(st + (uint32_t)(A_STAGE_H + row * PITCH_H + ch * 8) * 2,
                   g_Wh + (size_t)(n0 + row) * DDIM + kt * BK + ch * 8);
    }
}

__global__ void __launch_bounds__(GTHREADS, 2) s6_gemm(const float* __restrict__ x,
                                                       const float* __restrict__ b1,
                                                       float* __restrict__ y) {
    extern __shared__ __half smh[];
    const uint32_t sm_u = smem_u32(smh);

    const int tid = threadIdx.x;
    const int wid = tid >> 5;
    const int lane = tid & 31;
    const int grp = lane >> 2;
    const int qid = lane & 3;
    const int wm = wid & 1;      // 2 warps along M (64 each)
    const int wn = wid >> 1;     // 4 warps along N (16 each)
    const int m0 = blockIdx.y * BM;
    const int n0 = blockIdx.x * BN;

    float acc[4][2][4];
#pragma unroll
    for (int f = 0; f < 4; ++f)
#pragma unroll
        for (int g = 0; g < 2; ++g)
#pragma unroll
            for (int q = 0; q < 4; ++q) acc[f][g][q] = 0.0f;

    g_prefetch(sm_u, 0, 0, m0, n0, tid);
    cp_commit();
    g_prefetch(sm_u, 1, 1, m0, n0, tid);
    cp_commit();

    const int aRow = wm * 64 + grp;
    const int bRow = wn * 16 + grp;

    for (int kt = 0; kt < NKIT; ++kt) {
        const int s = kt % 3;
        cp_wait<1>();
        __syncthreads();

        const int pf = kt + 2;
        if (pf < NKIT) g_prefetch(sm_u, pf % 3, pf, m0, n0, tid);
        cp_commit();

        const __half* sAs = smh + s * G_STAGE_H;
        const __half* sBs = sAs + A_STAGE_H;
#pragma unroll
        for (int ks = 0; ks < 2; ++ks) {
            const int koff = ks * 16 + 2 * qid;
            uint32_t af[4][4], bf[2][2];
#pragma unroll
            for (int f = 0; f < 4; ++f) {
                const __half* p = sAs + (aRow + f * 16) * PITCH_H + koff;
                af[f][0] = *(const uint32_t*)p;
                af[f][1] = *(const uint32_t*)(p + 8 * PITCH_H);
                af[f][2] = *(const uint32_t*)(p + 8);
                af[f][3] = *(const uint32_t*)(p + 8 * PITCH_H + 8);
            }
#pragma unroll
            for (int g = 0; g < 2; ++g) {
                const __half* p = sBs + (bRow + g * 8) * PITCH_H + koff;
                bf[g][0] = *(const uint32_t*)p;
                bf[g][1] = *(const uint32_t*)(p + 8);
            }
#pragma unroll
            for (int f = 0; f < 4; ++f)
#pragma unroll
                for (int g = 0; g < 2; ++g)
                    mma_f16(acc[f][g], af[f], bf[g]);
        }
    }

    // fused epilogue: y = x * softplus(acc + b1) * s
#pragma unroll
    for (int f = 0; f < 4; ++f) {
        const int r0 = m0 + wm * 64 + f * 16 + grp;
        const int r1 = r0 + 8;
        const float s0 = __ldg(g_s + r0);
        const float s1 = __ldg(g_s + r1);
        const float* xr0 = x + (size_t)r0 * DDIM;
        const float* xr1 = x + (size_t)r1 * DDIM;
        float* yr0 = y + (size_t)r0 * DDIM;
        float* yr1 = y + (size_t)r1 * DDIM;
#pragma unroll
        for (int g = 0; g < 2; ++g) {
            const int c = n0 + wn * 16 + g * 8 + 2 * qid;
            const float2 bv = *(const float2*)(b1 + c);
            const float2 x0 = *(const float2*)(xr0 + c);
            const float2 x1 = *(const float2*)(xr1 + c);
            float2 o0, o1;
            o0.x = x0.x * softplus_f(acc[f][g][0] + bv.x) * s0;
            o0.y = x0.y * softplus_f(acc[f][g][1] + bv.y) * s0;
            o1.x = x1.x * softplus_f(acc[f][g][2] + bv.x) * s1;
            o1.y = x1.y * softplus_f(acc[f][g][3] + bv.y) * s1;
            *(float2*)(yr0 + c) = o0;
            *(float2*)(yr1 + c) = o1;
        }
    }
}

// ---------------------------------------------------------------------------
// Launch
// ---------------------------------------------------------------------------
extern "C" void kernel_launch(void* const* d_in, const int* in_sizes, int n_in,
                              void* d_out, int out_size) {
    const float* x  = (const float*)d_in[0];
    const float* W1 = (const float*)d_in[1];
    const float* b1 = (const float*)d_in[2];
    const float* W2 = (const float*)d_in[3];
    const float* b2 = (const float*)d_in[4];
    const float* W3 = (const float*)d_in[5];
    const float* b3 = (const float*)d_in[6];
    float* y = (float*)d_out;

    s6_pack_w23<<<128, 256>>>(W2, W3);
    s6_pack_w1<<<dim3(32, 32), dim3(32, 32)>>>(W1);
    s6_prep<<<NTOK / 32, 256>>>(x, b2, b3);

    cudaFuncSetAttribute(s6_gemm, cudaFuncAttributeMaxDynamicSharedMemorySize, G_SMEM_BYTES);
    s6_gemm<<<dim3(DDIM / BN, NTOK / BM), GTHREADS, G_SMEM_BYTES>>>(x, b1, y);
}

// round 6
// speedup vs baseline: 1.7424x; 1.1736x over previous
#include <cuda_runtime.h>
#include <cuda_fp16.h>
#include <cstdint>

// ============================================================================
// S6 forward, reduced:
//   y[t,d] = x[t,d] * softplus(U1[t,d] + b1[d]) * s[t]
//   s[t]   = sum_n (U2[t,n]+b2[n]) * (U3[t,n]+b3[n])
// Pipeline (fp16 tensor-core, fp32 accum; base sm_103 ISA — no tcgen05):
//   1. pack_w1:  W1 -> g_Wh [n][k] fp16 (transposed)
//   2. pack_w23: W2|W3 -> g_W23h [32][k] fp16
//   3. prep:     x -> g_Xh fp16  AND  g_s[t] (fused convert + skinny GEMM)
//   4. gemm:     128x128 tiles, ldmatrix + m16n8k16, fused epilogue -> y
// ============================================================================

#define NTOK   8192
#define DDIM   1024

#define BM     128
#define BN     128
#define BK     32
#define NKIT   (DDIM / BK)   // 32
#define GTHREADS 256

#define PITCH_H   40         // smem row pitch (halves) = 80B: 16B-aligned, ldmatrix conflict-free
#define A_STAGE_H (BM * PITCH_H)               // 5120 halves
#define B_STAGE_H (BN * PITCH_H)               // 5120 halves
#define G_STAGE_H (A_STAGE_H + B_STAGE_H)      // 10240
#define G_SMEM_BYTES (3 * G_STAGE_H * 2)       // 61440

__device__ __half g_Wh[(size_t)DDIM * DDIM];   // W1^T, [n][k], 2 MB
__device__ __half g_W23h[32 * DDIM];           // [n][k]: n<16 W2 col, n>=16 W3 col
__device__ __half g_Xh[(size_t)NTOK * DDIM];   // x fp16, 16.8 MB
__device__ float  g_s[NTOK];

// ---------------------------------------------------------------------------
// helpers
// ---------------------------------------------------------------------------
__device__ __forceinline__ uint32_t smem_u32(const void* p) {
    uint32_t a;
    asm("{ .reg .u64 t; cvta.to.shared.u64 t, %1; cvt.u32.u64 %0, t; }" : "=r"(a) : "l"(p));
    return a;
}
__device__ __forceinline__ uint32_t h2_u32(__half2 h) {
    union { __half2 h; uint32_t u; } cvt;
    cvt.h = h;
    return cvt.u;
}
__device__ __forceinline__ void cp_async16(uint32_t dst, const void* src) {
    asm volatile("cp.async.cg.shared.global [%0], [%1], 16;" :: "r"(dst), "l"(src) : "memory");
}
__device__ __forceinline__ void cp_commit() {
    asm volatile("cp.async.commit_group;" ::: "memory");
}
template <int N>
__device__ __forceinline__ void cp_wait() {
    asm volatile("cp.async.wait_group %0;" :: "n"(N) : "memory");
}
__device__ __forceinline__ void ldmx4(uint32_t* r, uint32_t addr) {
    asm volatile("ldmatrix.sync.aligned.m8n8.x4.shared.b16 {%0,%1,%2,%3}, [%4];"
        : "=r"(r[0]), "=r"(r[1]), "=r"(r[2]), "=r"(r[3]) : "r"(addr));
}
__device__ __forceinline__ void mma_f16(float* c, const uint32_t* a, const uint32_t* b) {
    asm volatile(
        "mma.sync.aligned.m16n8k16.row.col.f32.f16.f16.f32 "
        "{%0,%1,%2,%3}, {%4,%5,%6,%7}, {%8,%9}, {%0,%1,%2,%3};"
        : "+f"(c[0]), "+f"(c[1]), "+f"(c[2]), "+f"(c[3])
        : "r"(a[0]), "r"(a[1]), "r"(a[2]), "r"(a[3]), "r"(b[0]), "r"(b[1]));
}
__device__ __forceinline__ float softplus_f(float z) {
    return fmaxf(z, 0.0f) + __logf(1.0f + __expf(-fabsf(z)));
}

// ---------------------------------------------------------------------------
// Kernel 1a: Wh[n][k] = fp16(W1[k][n])
// ---------------------------------------------------------------------------
__global__ void __launch_bounds__(1024) s6_pack_w1(const float* __restrict__ W1) {
    __shared__ float tile[32][33];
    const int tx = threadIdx.x, ty = threadIdx.y;
    const int k = blockIdx.y * 32 + ty;
    const int n = blockIdx.x * 32 + tx;
    tile[ty][tx] = W1[(size_t)k * DDIM + n];
    __syncthreads();
    const int nn = blockIdx.x * 32 + ty;
    const int kk = blockIdx.y * 32 + tx;
    g_Wh[(size_t)nn * DDIM + kk] = __float2half_rn(tile[tx][ty]);
}

// ---------------------------------------------------------------------------
// Kernel 1b: W23h[n][k]
// ---------------------------------------------------------------------------
__global__ void __launch_bounds__(256) s6_pack_w23(const float* __restrict__ W2,
                                                   const float* __restrict__ W3) {
    const int idx = blockIdx.x * 256 + threadIdx.x;   // 32768
    const int n = idx >> 10;
    const int k = idx & 1023;
    const float v = (n < 16) ? W2[(size_t)k * 16 + n] : W3[(size_t)k * 16 + (n - 16)];
    g_W23h[n * DDIM + k] = __float2half_rn(v);
}

// ---------------------------------------------------------------------------
// Kernel 2: prep — fused x->fp16 convert + s[t] computation
// ---------------------------------------------------------------------------
#define P_PITCH 136
#define P_STG   (32 * P_PITCH)

__global__ void __launch_bounds__(256) s6_prep(const float* __restrict__ x,
                                               const float* __restrict__ b2,
                                               const float* __restrict__ b3) {
    __shared__ __half sX[2][P_STG];
    __shared__ __half sW[2][P_STG];
    __shared__ float sU[32][33];

    const int tid = threadIdx.x;
    const int wid = tid >> 5;
    const int lane = tid & 31;
    const int grp = lane >> 2;
    const int qid = lane & 3;
    const int tok0 = blockIdx.x * 32;
    const uint32_t sW_u[2] = { smem_u32(sW[0]), smem_u32(sW[1]) };

    for (int i = tid; i < 32 * 33; i += 256) ((float*)sU)[i] = 0.0f;

#pragma unroll
    for (int j = 0; j < 2; ++j) {
        const int i = tid + j * 256;
        const int row = i >> 4, ch = i & 15;
        cp_async16(sW_u[0] + (uint32_t)(row * P_PITCH + ch * 8) * 2,
                   g_W23h + row * DDIM + ch * 8);
    }
    cp_commit();

    const int t = tid >> 3;
    const int co = (tid & 7) * 16;

    float acc[2][4][4];
#pragma unroll
    for (int f = 0; f < 2; ++f)
#pragma unroll
        for (int g = 0; g < 4; ++g)
#pragma unroll
            for (int q = 0; q < 4; ++q) acc[f][g][q] = 0.0f;

    for (int c = 0; c < 8; ++c) {
        const int st = c & 1;
        const float* src = x + (size_t)(tok0 + t) * DDIM + c * 128 + co;
        float4 v0 = *(const float4*)(src + 0);
        float4 v1 = *(const float4*)(src + 4);
        float4 v2 = *(const float4*)(src + 8);
        float4 v3 = *(const float4*)(src + 12);
        uint4 pk0, pk1;
        pk0.x = h2_u32(__float22half2_rn(make_float2(v0.x, v0.y)));
        pk0.y = h2_u32(__float22half2_rn(make_float2(v0.z, v0.w)));
        pk0.z = h2_u32(__float22half2_rn(make_float2(v1.x, v1.y)));
        pk0.w = h2_u32(__float22half2_rn(make_float2(v1.z, v1.w)));
        pk1.x = h2_u32(__float22half2_rn(make_float2(v2.x, v2.y)));
        pk1.y = h2_u32(__float22half2_rn(make_float2(v2.z, v2.w)));
        pk1.z = h2_u32(__float22half2_rn(make_float2(v3.x, v3.y)));
        pk1.w = h2_u32(__float22half2_rn(make_float2(v3.z, v3.w)));
        *(uint4*)(&sX[st][t * P_PITCH + co])     = pk0;
        *(uint4*)(&sX[st][t * P_PITCH + co + 8]) = pk1;
        __half* gx = g_Xh + (size_t)(tok0 + t) * DDIM + c * 128 + co;
        *(uint4*)(gx)     = pk0;
        *(uint4*)(gx + 8) = pk1;

        cp_wait<0>();
        __syncthreads();

        if (c < 7) {
            const int ns = (c + 1) & 1;
#pragma unroll
            for (int j = 0; j < 2; ++j) {
                const int i = tid + j * 256;
                const int row = i >> 4, ch = i & 15;
                cp_async16(sW_u[ns] + (uint32_t)(row * P_PITCH + ch * 8) * 2,
                           g_W23h + row * DDIM + (c + 1) * 128 + ch * 8);
            }
            cp_commit();
        }

        const int koff = wid * 16 + 2 * qid;
#pragma unroll
        for (int f = 0; f < 2; ++f) {
            const __half* p = &sX[st][(f * 16 + grp) * P_PITCH + koff];
            uint32_t a[4];
            a[0] = *(const uint32_t*)p;
            a[1] = *(const uint32_t*)(p + 8 * P_PITCH);
            a[2] = *(const uint32_t*)(p + 8);
            a[3] = *(const uint32_t*)(p + 8 * P_PITCH + 8);
#pragma unroll
            for (int g = 0; g < 4; ++g) {
                const __half* q = &sW[st][(g * 8 + grp) * P_PITCH + koff];
                uint32_t b[2];
                b[0] = *(const uint32_t*)q;
                b[1] = *(const uint32_t*)(q + 8);
                mma_f16(acc[f][g], a, b);
            }
        }
        __syncthreads();
    }

#pragma unroll
    for (int f = 0; f < 2; ++f)
#pragma unroll
        for (int g = 0; g < 4; ++g) {
            atomicAdd(&sU[f * 16 + grp][g * 8 + 2 * qid],         acc[f][g][0]);
            atomicAdd(&sU[f * 16 + grp][g * 8 + 2 * qid + 1],     acc[f][g][1]);
            atomicAdd(&sU[f * 16 + grp + 8][g * 8 + 2 * qid],     acc[f][g][2]);
            atomicAdd(&sU[f * 16 + grp + 8][g * 8 + 2 * qid + 1], acc[f][g][3]);
        }
    __syncthreads();

    if (tid < 32) {
        float s = 0.0f;
#pragma unroll
        for (int n = 0; n < 16; ++n)
            s += (sU[tid][n] + __ldg(b2 + n)) * (sU[tid][n + 16] + __ldg(b3 + n));
        g_s[tok0 + tid] = s;
    }
}

// ---------------------------------------------------------------------------
// Kernel 3: main GEMM — 128x128 tile, ldmatrix fragments, fused epilogue
// ---------------------------------------------------------------------------
__device__ __forceinline__ void g_prefetch(uint32_t smem_base_u, int stage, int kt,
                                           int m0, int n0, int tid) {
    const uint32_t st = smem_base_u + (uint32_t)(stage * G_STAGE_H) * 2;
#pragma unroll
    for (int i = 0; i < 2; ++i) {           // A: 128 rows x 4 x 16B
        const int c = tid + i * GTHREADS;
        const int row = c >> 2, ch = c & 3;
        cp_async16(st + (uint32_t)(row * PITCH_H + ch * 8) * 2,
                   g_Xh + (size_t)(m0 + row) * DDIM + kt * BK + ch * 8);
    }
#pragma unroll
    for (int i = 0; i < 2; ++i) {           // B: 128 rows x 4 x 16B
        const int c = tid + i * GTHREADS;
        const int row = c >> 2, ch = c & 3;
        cp_async16(st + (uint32_t)(A_STAGE_H + row * PITCH_H + ch * 8) * 2,
                   g_Wh + (size_t)(n0 + row) * DDIM + kt * BK + ch * 8);
    }
}

__global__ void __launch_bounds__(GTHREADS, 2) s6_gemm(const float* __restrict__ x,
                                                       const float* __restrict__ b1,
                                                       float* __restrict__ y) {
    extern __shared__ __half smh[];
    const uint32_t sm_u = smem_u32(smh);

    const int tid = threadIdx.x;
    const int wid = tid >> 5;
    const int lane = tid & 31;
    const int grp = lane >> 2;
    const int qid = lane & 3;
    const int wm = wid & 1;      // 2 warps along M (64 each)
    const int wn = wid >> 1;     // 4 warps along N (32 each)
    const int m0 = blockIdx.y * BM;
    const int n0 = blockIdx.x * BN;

    // ldmatrix per-lane base offsets (half units within a stage)
    //  A: lanes 0-15 -> rows, lanes 16-31 -> +8 in k
    const uint32_t aIdx = (uint32_t)((wm * 64 + (lane & 15)) * PITCH_H + (lane >> 4) * 8);
    //  B: mat = lane>>3: n += (mat>>1)*8, k += (mat&1)*8
    const uint32_t bIdx = (uint32_t)(A_STAGE_H +
        (wn * 32 + ((lane >> 4) & 1) * 8 + (lane & 7)) * PITCH_H + ((lane >> 3) & 1) * 8);

    float acc[4][4][4];
#pragma unroll
    for (int f = 0; f < 4; ++f)
#pragma unroll
        for (int g = 0; g < 4; ++g)
#pragma unroll
            for (int q = 0; q < 4; ++q) acc[f][g][q] = 0.0f;

    g_prefetch(sm_u, 0, 0, m0, n0, tid);
    cp_commit();
    g_prefetch(sm_u, 1, 1, m0, n0, tid);
    cp_commit();

    for (int kt = 0; kt < NKIT; ++kt) {
        const int s = kt % 3;
        cp_wait<1>();
        __syncthreads();

        const int pf = kt + 2;
        if (pf < NKIT) g_prefetch(sm_u, pf % 3, pf, m0, n0, tid);
        cp_commit();

        const uint32_t stg = sm_u + (uint32_t)(s * G_STAGE_H) * 2;
#pragma unroll
        for (int ks = 0; ks < 2; ++ks) {
            uint32_t af[4][4], bf[4][2];
#pragma unroll
            for (int f = 0; f < 4; ++f)
                ldmx4(af[f], stg + (aIdx + (uint32_t)(f * 16 * PITCH_H + ks * 16)) * 2);
#pragma unroll
            for (int h = 0; h < 2; ++h) {
                uint32_t bq[4];
                ldmx4(bq, stg + (bIdx + (uint32_t)(h * 16 * PITCH_H + ks * 16)) * 2);
                bf[2 * h][0]     = bq[0];
                bf[2 * h][1]     = bq[1];
                bf[2 * h + 1][0] = bq[2];
                bf[2 * h + 1][1] = bq[3];
            }
#pragma unroll
            for (int f = 0; f < 4; ++f)
#pragma unroll
                for (int g = 0; g < 4; ++g)
                    mma_f16(acc[f][g], af[f], bf[g]);
        }
    }

    // fused epilogue: y = x * softplus(acc + b1) * s
#pragma unroll
    for (int f = 0; f < 4; ++f) {
        const int r0 = m0 + wm * 64 + f * 16 + grp;
        const int r1 = r0 + 8;
        const float s0 = __ldg(g_s + r0);
        const float s1 = __ldg(g_s + r1);
        const float* xr0 = x + (size_t)r0 * DDIM;
        const float* xr1 = x + (size_t)r1 * DDIM;
        float* yr0 = y + (size_t)r0 * DDIM;
        float* yr1 = y + (size_t)r1 * DDIM;
#pragma unroll
        for (int g = 0; g < 4; ++g) {
            const int c = n0 + wn * 32 + g * 8 + 2 * qid;
            const float2 bv = *(const float2*)(b1 + c);
            const float2 x0 = *(const float2*)(xr0 + c);
            const float2 x1 = *(const float2*)(xr1 + c);
            float2 o0, o1;
            o0.x = x0.x * softplus_f(acc[f][g][0] + bv.x) * s0;
            o0.y = x0.y * softplus_f(acc[f][g][1] + bv.y) * s0;
            o1.x = x1.x * softplus_f(acc[f][g][2] + bv.x) * s1;
            o1.y = x1.y * softplus_f(acc[f][g][3] + bv.y) * s1;
            *(float2*)(yr0 + c) = o0;
            *(float2*)(yr1 + c) = o1;
        }
    }
}

// ---------------------------------------------------------------------------
// Launch
// ---------------------------------------------------------------------------
extern "C" void kernel_launch(void* const* d_in, const int* in_sizes, int n_in,
                              void* d_out, int out_size) {
    const float* x  = (const float*)d_in[0];
    const float* W1 = (const float*)d_in[1];
    const float* b1 = (const float*)d_in[2];
    const float* W2 = (const float*)d_in[3];
    const float* b2 = (const float*)d_in[4];
    const float* W3 = (const float*)d_in[5];
    const float* b3 = (const float*)d_in[6];
    float* y = (float*)d_out;

    s6_pack_w23<<<128, 256>>>(W2, W3);
    s6_pack_w1<<<dim3(32, 32), dim3(32, 32)>>>(W1);
    s6_prep<<<NTOK / 32, 256>>>(x, b2, b3);

    cudaFuncSetAttribute(s6_gemm, cudaFuncAttributeMaxDynamicSharedMemorySize, G_SMEM_BYTES);
    s6_gemm<<<dim3(DDIM / BN, NTOK / BM), GTHREADS, G_SMEM_BYTES>>>(x, b1, y);
}

// round 7
// speedup vs baseline: 1.8713x; 1.0740x over previous
#include <cuda_runtime.h>
#include <cuda_fp16.h>
#include <cstdint>

// ============================================================================
// S6 forward, reduced:
//   y[t,d] = x[t,d] * softplus(U1[t,d] + b1[d]) * s[t]
//   s[t]   = sum_n (U2[t,n]+b2[n]) * (U3[t,n]+b3[n])
// Pipeline (fp16 tensor-core, fp32 accum; base sm_103 ISA — no tcgen05):
//   1. pack_w1:  W1 -> g_Wh [n][k] fp16 (transposed)
//   2. pack_w23: W2|W3 -> g_W23h [32][k] fp16
//   3. prep:     x -> g_Xh fp16  AND  g_s[t] (fused convert + skinny GEMM)
//   4. gemm:     128x128 CTA tile, 4 warps @ 64x64 warp tile, ldmatrix,
//                4-stage cp.async, fused epilogue -> y
// ============================================================================

#define NTOK   8192
#define DDIM   1024

#define BM     128
#define BN     128
#define BK     32
#define NKIT   (DDIM / BK)   // 32
#define GTHREADS 128         // 4 warps, 2x2 warp grid, 64x64 per warp

#define PITCH_H   40         // smem row pitch (halves) = 80B: 16B-aligned, ldmatrix conflict-free
#define A_STAGE_H (BM * PITCH_H)               // 5120 halves
#define B_STAGE_H (BN * PITCH_H)               // 5120 halves
#define G_STAGE_H (A_STAGE_H + B_STAGE_H)      // 10240
#define STAGES    4
#define G_SMEM_BYTES (STAGES * G_STAGE_H * 2)  // 81920

__device__ __half g_Wh[(size_t)DDIM * DDIM];   // W1^T, [n][k], 2 MB
__device__ __half g_W23h[32 * DDIM];           // [n][k]: n<16 W2 col, n>=16 W3 col
__device__ __half g_Xh[(size_t)NTOK * DDIM];   // x fp16, 16.8 MB
__device__ float  g_s[NTOK];

// ---------------------------------------------------------------------------
// helpers
// ---------------------------------------------------------------------------
__device__ __forceinline__ uint32_t smem_u32(const void* p) {
    uint32_t a;
    asm("{ .reg .u64 t; cvta.to.shared.u64 t, %1; cvt.u32.u64 %0, t; }" : "=r"(a) : "l"(p));
    return a;
}
__device__ __forceinline__ uint32_t h2_u32(__half2 h) {
    union { __half2 h; uint32_t u; } cvt;
    cvt.h = h;
    return cvt.u;
}
__device__ __forceinline__ void cp_async16(uint32_t dst, const void* src) {
    asm volatile("cp.async.cg.shared.global [%0], [%1], 16;" :: "r"(dst), "l"(src) : "memory");
}
__device__ __forceinline__ void cp_commit() {
    asm volatile("cp.async.commit_group;" ::: "memory");
}
template <int N>
__device__ __forceinline__ void cp_wait() {
    asm volatile("cp.async.wait_group %0;" :: "n"(N) : "memory");
}
__device__ __forceinline__ void ldmx4(uint32_t* r, uint32_t addr) {
    asm volatile("ldmatrix.sync.aligned.m8n8.x4.shared.b16 {%0,%1,%2,%3}, [%4];"
        : "=r"(r[0]), "=r"(r[1]), "=r"(r[2]), "=r"(r[3]) : "r"(addr));
}
__device__ __forceinline__ void mma_f16(float* c, const uint32_t* a, const uint32_t* b) {
    asm volatile(
        "mma.sync.aligned.m16n8k16.row.col.f32.f16.f16.f32 "
        "{%0,%1,%2,%3}, {%4,%5,%6,%7}, {%8,%9}, {%0,%1,%2,%3};"
        : "+f"(c[0]), "+f"(c[1]), "+f"(c[2]), "+f"(c[3])
        : "r"(a[0]), "r"(a[1]), "r"(a[2]), "r"(a[3]), "r"(b[0]), "r"(b[1]));
}
__device__ __forceinline__ float softplus_f(float z) {
    return fmaxf(z, 0.0f) + __logf(1.0f + __expf(-fabsf(z)));
}

// ---------------------------------------------------------------------------
// Kernel 1a: Wh[n][k] = fp16(W1[k][n])
// ---------------------------------------------------------------------------
__global__ void __launch_bounds__(1024) s6_pack_w1(const float* __restrict__ W1) {
    __shared__ float tile[32][33];
    const int tx = threadIdx.x, ty = threadIdx.y;
    const int k = blockIdx.y * 32 + ty;
    const int n = blockIdx.x * 32 + tx;
    tile[ty][tx] = W1[(size_t)k * DDIM + n];
    __syncthreads();
    const int nn = blockIdx.x * 32 + ty;
    const int kk = blockIdx.y * 32 + tx;
    g_Wh[(size_t)nn * DDIM + kk] = __float2half_rn(tile[tx][ty]);
}

// ---------------------------------------------------------------------------
// Kernel 1b: W23h[n][k]
// ---------------------------------------------------------------------------
__global__ void __launch_bounds__(256) s6_pack_w23(const float* __restrict__ W2,
                                                   const float* __restrict__ W3) {
    const int idx = blockIdx.x * 256 + threadIdx.x;   // 32768
    const int n = idx >> 10;
    const int k = idx & 1023;
    const float v = (n < 16) ? W2[(size_t)k * 16 + n] : W3[(size_t)k * 16 + (n - 16)];
    g_W23h[n * DDIM + k] = __float2half_rn(v);
}

// ---------------------------------------------------------------------------
// Kernel 2: prep — fused x->fp16 convert + s[t] computation
// ---------------------------------------------------------------------------
#define P_PITCH 136
#define P_STG   (32 * P_PITCH)

__global__ void __launch_bounds__(256) s6_prep(const float* __restrict__ x,
                                               const float* __restrict__ b2,
                                               const float* __restrict__ b3) {
    __shared__ __half sX[2][P_STG];
    __shared__ __half sW[2][P_STG];
    __shared__ float sU[32][33];

    const int tid = threadIdx.x;
    const int wid = tid >> 5;
    const int lane = tid & 31;
    const int grp = lane >> 2;
    const int qid = lane & 3;
    const int tok0 = blockIdx.x * 32;
    const uint32_t sW_u[2] = { smem_u32(sW[0]), smem_u32(sW[1]) };

    for (int i = tid; i < 32 * 33; i += 256) ((float*)sU)[i] = 0.0f;

#pragma unroll
    for (int j = 0; j < 2; ++j) {
        const int i = tid + j * 256;
        const int row = i >> 4, ch = i & 15;
        cp_async16(sW_u[0] + (uint32_t)(row * P_PITCH + ch * 8) * 2,
                   g_W23h + row * DDIM + ch * 8);
    }
    cp_commit();

    const int t = tid >> 3;
    const int co = (tid & 7) * 16;

    float acc[2][4][4];
#pragma unroll
    for (int f = 0; f < 2; ++f)
#pragma unroll
        for (int g = 0; g < 4; ++g)
#pragma unroll
            for (int q = 0; q < 4; ++q) acc[f][g][q] = 0.0f;

    for (int c = 0; c < 8; ++c) {
        const int st = c & 1;
        const float* src = x + (size_t)(tok0 + t) * DDIM + c * 128 + co;
        float4 v0 = *(const float4*)(src + 0);
        float4 v1 = *(const float4*)(src + 4);
        float4 v2 = *(const float4*)(src + 8);
        float4 v3 = *(const float4*)(src + 12);
        uint4 pk0, pk1;
        pk0.x = h2_u32(__float22half2_rn(make_float2(v0.x, v0.y)));
        pk0.y = h2_u32(__float22half2_rn(make_float2(v0.z, v0.w)));
        pk0.z = h2_u32(__float22half2_rn(make_float2(v1.x, v1.y)));
        pk0.w = h2_u32(__float22half2_rn(make_float2(v1.z, v1.w)));
        pk1.x = h2_u32(__float22half2_rn(make_float2(v2.x, v2.y)));
        pk1.y = h2_u32(__float22half2_rn(make_float2(v2.z, v2.w)));
        pk1.z = h2_u32(__float22half2_rn(make_float2(v3.x, v3.y)));
        pk1.w = h2_u32(__float22half2_rn(make_float2(v3.z, v3.w)));
        *(uint4*)(&sX[st][t * P_PITCH + co])     = pk0;
        *(uint4*)(&sX[st][t * P_PITCH + co + 8]) = pk1;
        __half* gx = g_Xh + (size_t)(tok0 + t) * DDIM + c * 128 + co;
        *(uint4*)(gx)     = pk0;
        *(uint4*)(gx + 8) = pk1;

        cp_wait<0>();
        __syncthreads();

        if (c < 7) {
            const int ns = (c + 1) & 1;
#pragma unroll
            for (int j = 0; j < 2; ++j) {
                const int i = tid + j * 256;
                const int row = i >> 4, ch = i & 15;
                cp_async16(sW_u[ns] + (uint32_t)(row * P_PITCH + ch * 8) * 2,
                           g_W23h + row * DDIM + (c + 1) * 128 + ch * 8);
            }
            cp_commit();
        }

        const int koff = wid * 16 + 2 * qid;
#pragma unroll
        for (int f = 0; f < 2; ++f) {
            const __half* p = &sX[st][(f * 16 + grp) * P_PITCH + koff];
            uint32_t a[4];
            a[0] = *(const uint32_t*)p;
            a[1] = *(const uint32_t*)(p + 8 * P_PITCH);
            a[2] = *(const uint32_t*)(p + 8);
            a[3] = *(const uint32_t*)(p + 8 * P_PITCH + 8);
#pragma unroll
            for (int g = 0; g < 4; ++g) {
                const __half* q = &sW[st][(g * 8 + grp) * P_PITCH + koff];
                uint32_t b[2];
                b[0] = *(const uint32_t*)q;
                b[1] = *(const uint32_t*)(q + 8);
                mma_f16(acc[f][g], a, b);
            }
        }
        __syncthreads();
    }

#pragma unroll
    for (int f = 0; f < 2; ++f)
#pragma unroll
        for (int g = 0; g < 4; ++g) {
            atomicAdd(&sU[f * 16 + grp][g * 8 + 2 * qid],         acc[f][g][0]);
            atomicAdd(&sU[f * 16 + grp][g * 8 + 2 * qid + 1],     acc[f][g][1]);
            atomicAdd(&sU[f * 16 + grp + 8][g * 8 + 2 * qid],     acc[f][g][2]);
            atomicAdd(&sU[f * 16 + grp + 8][g * 8 + 2 * qid + 1], acc[f][g][3]);
        }
    __syncthreads();

    if (tid < 32) {
        float s = 0.0f;
#pragma unroll
        for (int n = 0; n < 16; ++n)
            s += (sU[tid][n] + __ldg(b2 + n)) * (sU[tid][n + 16] + __ldg(b3 + n));
        g_s[tok0 + tid] = s;
    }
}

// ---------------------------------------------------------------------------
// Kernel 3: main GEMM — 128x128 tile, 4 warps @ 64x64, ldmatrix, 4 stages
// ---------------------------------------------------------------------------
__device__ __forceinline__ void g_prefetch(uint32_t smem_base_u, int stage, int kt,
                                           int m0, int n0, int tid) {
    const uint32_t st = smem_base_u + (uint32_t)(stage * G_STAGE_H) * 2;
#pragma unroll
    for (int i = 0; i < 4; ++i) {           // A: 128 rows x 4 x 16B
        const int c = tid + i * GTHREADS;
        const int row = c >> 2, ch = c & 3;
        cp_async16(st + (uint32_t)(row * PITCH_H + ch * 8) * 2,
                   g_Xh + (size_t)(m0 + row) * DDIM + kt * BK + ch * 8);
    }
#pragma unroll
    for (int i = 0; i < 4; ++i) {           // B: 128 rows x 4 x 16B
        const int c = tid + i * GTHREADS;
        const int row = c >> 2, ch = c & 3;
        cp_async16(st + (uint32_t)(A_STAGE_H + row * PITCH_H + ch * 8) * 2,
                   g_Wh + (size_t)(n0 + row) * DDIM + kt * BK + ch * 8);
    }
}

__global__ void __launch_bounds__(GTHREADS, 2) s6_gemm(const float* __restrict__ x,
                                                       const float* __restrict__ b1,
                                                       float* __restrict__ y) {
    extern __shared__ __half smh[];
    const uint32_t sm_u = smem_u32(smh);

    const int tid = threadIdx.x;
    const int wid = tid >> 5;
    const int lane = tid & 31;
    const int grp = lane >> 2;
    const int qid = lane & 3;
    const int wm = wid & 1;      // 2 warps along M (64 each)
    const int wn = wid >> 1;     // 2 warps along N (64 each)
    const int m0 = blockIdx.y * BM;
    const int n0 = blockIdx.x * BN;

    // ldmatrix per-lane base offsets (half units within a stage)
    const uint32_t aIdx = (uint32_t)((wm * 64 + (lane & 15)) * PITCH_H + (lane >> 4) * 8);
    const uint32_t bIdx = (uint32_t)(A_STAGE_H +
        (wn * 64 + ((lane >> 4) & 1) * 8 + (lane & 7)) * PITCH_H + ((lane >> 3) & 1) * 8);

    float acc[4][8][4];
#pragma unroll
    for (int f = 0; f < 4; ++f)
#pragma unroll
        for (int g = 0; g < 8; ++g)
#pragma unroll
            for (int q = 0; q < 4; ++q) acc[f][g][q] = 0.0f;

    g_prefetch(sm_u, 0, 0, m0, n0, tid);
    cp_commit();
    g_prefetch(sm_u, 1, 1, m0, n0, tid);
    cp_commit();
    g_prefetch(sm_u, 2, 2, m0, n0, tid);
    cp_commit();

    for (int kt = 0; kt < NKIT; ++kt) {
        const int s = kt % STAGES;
        cp_wait<2>();
        __syncthreads();

        const int pf = kt + 3;
        if (pf < NKIT) g_prefetch(sm_u, pf % STAGES, pf, m0, n0, tid);
        cp_commit();

        const uint32_t stg = sm_u + (uint32_t)(s * G_STAGE_H) * 2;
#pragma unroll
        for (int ks = 0; ks < 2; ++ks) {
            uint32_t af[4][4], bf[8][2];
#pragma unroll
            for (int f = 0; f < 4; ++f)
                ldmx4(af[f], stg + (aIdx + (uint32_t)(f * 16 * PITCH_H + ks * 16)) * 2);
#pragma unroll
            for (int h = 0; h < 4; ++h) {
                uint32_t bq[4];
                ldmx4(bq, stg + (bIdx + (uint32_t)(h * 16 * PITCH_H + ks * 16)) * 2);
                bf[2 * h][0]     = bq[0];
                bf[2 * h][1]     = bq[1];
                bf[2 * h + 1][0] = bq[2];
                bf[2 * h + 1][1] = bq[3];
            }
#pragma unroll
            for (int f = 0; f < 4; ++f)
#pragma unroll
                for (int g = 0; g < 8; ++g)
                    mma_f16(acc[f][g], af[f], bf[g]);
        }
    }

    // fused epilogue: y = x * softplus(acc + b1) * s
#pragma unroll
    for (int f = 0; f < 4; ++f) {
        const int r0 = m0 + wm * 64 + f * 16 + grp;
        const int r1 = r0 + 8;
        const float s0 = __ldg(g_s + r0);
        const float s1 = __ldg(g_s + r1);
        const float* xr0 = x + (size_t)r0 * DDIM;
        const float* xr1 = x + (size_t)r1 * DDIM;
        float* yr0 = y + (size_t)r0 * DDIM;
        float* yr1 = y + (size_t)r1 * DDIM;
#pragma unroll
        for (int g = 0; g < 8; ++g) {
            const int c = n0 + wn * 64 + g * 8 + 2 * qid;
            const float2 bv = *(const float2*)(b1 + c);
            const float2 x0 = *(const float2*)(xr0 + c);
            const float2 x1 = *(const float2*)(xr1 + c);
            float2 o0, o1;
            o0.x = x0.x * softplus_f(acc[f][g][0] + bv.x) * s0;
            o0.y = x0.y * softplus_f(acc[f][g][1] + bv.y) * s0;
            o1.x = x1.x * softplus_f(acc[f][g][2] + bv.x) * s1;
            o1.y = x1.y * softplus_f(acc[f][g][3] + bv.y) * s1;
            *(float2*)(yr0 + c) = o0;
            *(float2*)(yr1 + c) = o1;
        }
    }
}

// ---------------------------------------------------------------------------
// Launch
// ---------------------------------------------------------------------------
extern "C" void kernel_launch(void* const* d_in, const int* in_sizes, int n_in,
                              void* d_out, int out_size) {
    const float* x  = (const float*)d_in[0];
    const float* W1 = (const float*)d_in[1];
    const float* b1 = (const float*)d_in[2];
    const float* W2 = (const float*)d_in[3];
    const float* b2 = (const float*)d_in[4];
    const float* W3 = (const float*)d_in[5];
    const float* b3 = (const float*)d_in[6];
    float* y = (float*)d_out;

    s6_pack_w23<<<128, 256>>>(W2, W3);
    s6_pack_w1<<<dim3(32, 32), dim3(32, 32)>>>(W1);
    s6_prep<<<NTOK / 32, 256>>>(x, b2, b3);

    cudaFuncSetAttribute(s6_gemm, cudaFuncAttributeMaxDynamicSharedMemorySize, G_SMEM_BYTES);
    s6_gemm<<<dim3(DDIM / BN, NTOK / BM), GTHREADS, G_SMEM_BYTES>>>(x, b1, y);
}